// round 1
// baseline (speedup 1.0000x reference)
#include <cuda_runtime.h>
#include <math.h>

// Problem constants
#define TSTEPS 128
#define BSZ    64
#define FSZ    1024
#define HSZ    1024
#define N4H    4096   // 4*H

// ---------------- device scratch (static: no runtime allocation) ----------------
__device__ float g_Z[(size_t)TSTEPS * BSZ * N4H];   // [T][B][4H]  precomputed x@Wx + b   (128 MB)
__device__ float g_Wr[128 * 1024 * 32];             // [blk][k][gate*8+j] reordered W_h   (16 MB)
__device__ float g_h[2][BSZ * HSZ];                 // double-buffered hidden state
__device__ float g_c[BSZ * HSZ];                    // cell state

// ---------------- init: zero c and h[0] ----------------
__global__ void init_state_kernel() {
    int i = blockIdx.x * blockDim.x + threadIdx.x;
    if (i < BSZ * HSZ) {
        g_c[i] = 0.0f;
        g_h[0][i] = 0.0f;
    }
}

// ---------------- reorder W_h into per-block gate-interleaved panels ----------------
// g_Wr[blk][k][g*8+j] = W[(F + k)][g*H + blk*8 + j]
__global__ void reorder_W_kernel(const float* __restrict__ W) {
    int idx = blockIdx.x * blockDim.x + threadIdx.x;   // over 128*1024*32
    int c   = idx & 31;
    int k   = (idx >> 5) & 1023;
    int blk = idx >> 15;
    int g = c >> 3;
    int j = c & 7;
    g_Wr[idx] = W[(size_t)(FSZ + k) * N4H + g * HSZ + blk * 8 + j];
}

// ---------------- precompute Z = X @ Wx + b ----------------
// A = x viewed as [M=8192][K=1024] (m = b*T + t, natural layout of x[B][T][F])
// B = W rows [0..F) : [K][N4H] row-major
// C written to g_Z[t][b][n]
// Tile: BM=128, BN=64, BK=32, 256 threads (16x16), thread tile 8x4.
__global__ __launch_bounds__(256, 2)
void precompute_kernel(const float* __restrict__ X, const float* __restrict__ W,
                       const float* __restrict__ bias) {
    __shared__ float As[32][129];   // [k][m] transposed, padded
    __shared__ float Bs[32][64];    // [k][n]

    const int tid = threadIdx.x;
    const int tx = tid & 15;        // col group (0..15), TN=4
    const int ty = tid >> 4;        // row group (0..15), TM=8
    const int m0 = blockIdx.y * 128;
    const int n0 = blockIdx.x * 64;

    float acc[8][4];
#pragma unroll
    for (int r = 0; r < 8; r++)
#pragma unroll
        for (int c = 0; c < 4; c++) acc[r][c] = 0.0f;

    for (int k0 = 0; k0 < FSZ; k0 += 32) {
        // load A tile: 128 rows x 32 k = 1024 float4, 4 per thread
#pragma unroll
        for (int i = 0; i < 4; i++) {
            int li = tid + i * 256;          // float4 index
            int row = li >> 3;               // 8 float4 per row
            int kq  = (li & 7) << 2;
            float4 v = *(const float4*)(X + (size_t)(m0 + row) * FSZ + k0 + kq);
            As[kq + 0][row] = v.x;
            As[kq + 1][row] = v.y;
            As[kq + 2][row] = v.z;
            As[kq + 3][row] = v.w;
        }
        // load B tile: 32 k x 64 n = 512 float4, 2 per thread
#pragma unroll
        for (int i = 0; i < 2; i++) {
            int li = tid + i * 256;
            int kk = li >> 4;                // 16 float4 per row
            int cq = (li & 15) << 2;
            float4 v = *(const float4*)(W + (size_t)(k0 + kk) * N4H + n0 + cq);
            *(float4*)&Bs[kk][cq] = v;
        }
        __syncthreads();

#pragma unroll
        for (int kk = 0; kk < 32; kk++) {
            float a_frag[8], b_frag[4];
#pragma unroll
            for (int r = 0; r < 8; r++) a_frag[r] = As[kk][ty * 8 + r];
#pragma unroll
            for (int c = 0; c < 4; c++) b_frag[c] = Bs[kk][tx * 4 + c];
#pragma unroll
            for (int r = 0; r < 8; r++)
#pragma unroll
                for (int c = 0; c < 4; c++) acc[r][c] += a_frag[r] * b_frag[c];
        }
        __syncthreads();
    }

    // epilogue: write into g_Z[t][b][n] with bias
#pragma unroll
    for (int r = 0; r < 8; r++) {
        int m = m0 + ty * 8 + r;
        int t = m & (TSTEPS - 1);
        int bb = m >> 7;
        float* zr = g_Z + ((size_t)t * BSZ + bb) * N4H;
#pragma unroll
        for (int c = 0; c < 4; c++) {
            int n = n0 + tx * 4 + c;
            zr[n] = acc[r][c] + bias[n];
        }
    }
}

// ---------------- fused recurrent step ----------------
// grid = 128 blocks; block `blk` owns H-columns [blk*8, blk*8+8) of all 4 gates.
// Computes S[64 rows][32 gate-cols] = h_in @ Wr_blk, adds precomputed Z, applies
// gates, updates c/h, writes output.
__global__ __launch_bounds__(256, 1)
void lstm_step_kernel(float* __restrict__ d_out, int t, int p) {
    __shared__ float As[64][65];   // [k][row] h tile (transposed, padded)
    __shared__ float Ws[64][32];   // [k][gatecol]
    __shared__ float Ss[64][33];   // result tile

    const float* __restrict__ hi = g_h[p];
    float* __restrict__ ho = g_h[p ^ 1];

    const int tid = threadIdx.x;
    const int tx = tid & 31;      // gate-col 0..31
    const int ty = tid >> 5;      // row group 0..7 (8 rows each)
    const int blk = blockIdx.x;
    const float* __restrict__ wr = g_Wr + (size_t)blk * 1024 * 32;

    float acc[8];
#pragma unroll
    for (int r = 0; r < 8; r++) acc[r] = 0.0f;

    for (int k0 = 0; k0 < HSZ; k0 += 64) {
        // load h tile: 64 rows x 64 k = 1024 float4, 4 per thread
#pragma unroll
        for (int i = 0; i < 4; i++) {
            int li = tid + i * 256;
            int row = li >> 4;              // 16 float4 per row
            int kq  = (li & 15) << 2;
            float4 v = *(const float4*)(hi + (size_t)row * HSZ + k0 + kq);
            As[kq + 0][row] = v.x;
            As[kq + 1][row] = v.y;
            As[kq + 2][row] = v.z;
            As[kq + 3][row] = v.w;
        }
        // load W tile: 64 k x 32 cols = 512 float4, 2 per thread (fully contiguous)
#pragma unroll
        for (int i = 0; i < 2; i++) {
            int li = tid + i * 256;
            int kk = li >> 3;               // 8 float4 per k-row
            int cq = (li & 7) << 2;
            float4 v = *(const float4*)(wr + (size_t)(k0 + kk) * 32 + cq);
            *(float4*)&Ws[kk][cq] = v;
        }
        __syncthreads();

#pragma unroll
        for (int kk = 0; kk < 64; kk++) {
            float wv = Ws[kk][tx];
#pragma unroll
            for (int r = 0; r < 8; r++) acc[r] += As[kk][ty * 8 + r] * wv;
        }
        __syncthreads();
    }

    // stash results for gate recombination
#pragma unroll
    for (int r = 0; r < 8; r++) Ss[ty * 8 + r][tx] = acc[r];
    __syncthreads();

    // epilogue: 64 rows x 8 hcols = 512 cells, 2 per thread
#pragma unroll
    for (int i = 0; i < 2; i++) {
        int cell = tid + i * 256;
        int row = cell >> 3;            // batch index 0..63
        int j   = cell & 7;
        int hcol = blk * 8 + j;
        const float* zrow = g_Z + ((size_t)t * BSZ + row) * N4H;

        float zi = Ss[row][j]      + zrow[0 * HSZ + hcol];
        float zj = Ss[row][8 + j]  + zrow[1 * HSZ + hcol];
        float zf = Ss[row][16 + j] + zrow[2 * HSZ + hcol];
        float zo = Ss[row][24 + j] + zrow[3 * HSZ + hcol];

        float c_old = g_c[(size_t)row * HSZ + hcol];
        float si = 1.0f / (1.0f + __expf(-zi));
        float sf = 1.0f / (1.0f + __expf(-(zf + 1.0f)));   // forget bias = 1.0
        float so = 1.0f / (1.0f + __expf(-zo));
        float tj = tanhf(zj);

        float c_new = c_old * sf + si * tj;
        float h_new = tanhf(c_new) * so;

        g_c[(size_t)row * HSZ + hcol] = c_new;
        ho[(size_t)row * HSZ + hcol]  = h_new;
        d_out[((size_t)row * TSTEPS + t) * HSZ + hcol] = h_new;
    }
}

// ---------------- launcher ----------------
extern "C" void kernel_launch(void* const* d_in, const int* in_sizes, int n_in,
                              void* d_out, int out_size) {
    const float* x = (const float*)d_in[0];   // [B, T, F]
    const float* W = (const float*)d_in[1];   // [F+H, 4H]
    const float* b = (const float*)d_in[2];   // [4H]
    float* out = (float*)d_out;               // [B, T, H]

    // 1. zero recurrent state
    init_state_kernel<<<(BSZ * HSZ + 255) / 256, 256>>>();

    // 2. reorder W_h into per-block panels
    reorder_W_kernel<<<(128 * 1024 * 32) / 256, 256>>>(W);

    // 3. precompute Z = x @ Wx + b for all timesteps
    {
        dim3 grid(N4H / 64, (BSZ * TSTEPS) / 128);   // (64, 64)
        precompute_kernel<<<grid, 256>>>(x, W, b);
    }

    // 4. sequential recurrence, one fused kernel per step
    for (int t = 0; t < TSTEPS; t++) {
        lstm_step_kernel<<<128, 256>>>(out, t, t & 1);
    }
}

// round 3
// speedup vs baseline: 1.7092x; 1.7092x over previous
#include <cuda_runtime.h>
#include <cstdint>
#include <math.h>

// Problem constants
#define TSTEPS 128
#define BSZ    64
#define FSZ    1024
#define HSZ    1024
#define N4H    4096   // 4*H

// Step-GEMM tiling
#define NCTA   64          // CTAs per step; each owns 16 hcols x 4 gates = 64 gate-rows
#define MT     64          // M per CTA (gate-rows)
#define NT     64          // N per CTA (batch)
#define KT     64          // K tile
#define NKT    (HSZ / KT)  // 16 k-tiles
// stage = A tile (64x64 f32 = 16KB) + B tile (16KB)
#define A_TILE_BYTES 16384
#define STAGE_BYTES  32768
#define DSMEM_BYTES  (2 * STAGE_BYTES + 1024)

// ---------------- device scratch ----------------
__device__ float g_Z[(size_t)TSTEPS * BSZ * N4H];      // [T][B][4H] precomputed x@Wx + b (128 MB)
__device__ float g_Wr[(size_t)NCTA * MT * HSZ];        // [blk][m][k] tf32-rounded recurrent weights (16 MB)
__device__ float g_h[2][BSZ * HSZ];
__device__ float g_c[BSZ * HSZ];

// ---------------- helpers ----------------
__device__ __forceinline__ uint32_t smem_u32(const void* p) {
    uint32_t a;
    asm("{ .reg .u64 t; cvta.to.shared.u64 t, %1; cvt.u32.u64 %0, t; }" : "=r"(a) : "l"(p));
    return a;
}
__device__ __forceinline__ uint32_t tf32r(float v) {
    uint32_t o;
    asm("cvt.rna.tf32.f32 %0, %1;" : "=r"(o) : "f"(v));
    return o;
}
#define CP16(dst, src) \
    asm volatile("cp.async.cg.shared.global [%0], [%1], 16;" :: "r"(dst), "l"(src) : "memory")
#define CP_COMMIT() asm volatile("cp.async.commit_group;" ::: "memory")
#define CP_WAIT1()  asm volatile("cp.async.wait_group 1;" ::: "memory")
#define CP_WAIT0()  asm volatile("cp.async.wait_group 0;" ::: "memory")

#define LDSM_X4(r0, r1, r2, r3, addr) \
    asm volatile("ldmatrix.sync.aligned.m8n8.x4.shared.b16 {%0,%1,%2,%3}, [%4];" \
                 : "=r"(r0), "=r"(r1), "=r"(r2), "=r"(r3) : "r"(addr))

#define MMA_TF32(c, a0, a1, a2, a3, b0, b1) \
    asm volatile("mma.sync.aligned.m16n8k8.row.col.f32.tf32.tf32.f32 " \
                 "{%0,%1,%2,%3}, {%4,%5,%6,%7}, {%8,%9}, {%0,%1,%2,%3};" \
                 : "+f"((c)[0]), "+f"((c)[1]), "+f"((c)[2]), "+f"((c)[3]) \
                 : "r"(a0), "r"(a1), "r"(a2), "r"(a3), "r"(b0), "r"(b1))

// ---------------- init: zero c and h[0] ----------------
__global__ void init_state_kernel() {
    int i = blockIdx.x * blockDim.x + threadIdx.x;
    if (i < BSZ * HSZ) { g_c[i] = 0.0f; g_h[0][i] = 0.0f; }
}

// ---------------- prep: transpose recurrent weights into [blk][m][k], tf32-rounded ----------------
// out[blk][m=g*16+j][k] = tf32(W[(F+k)][g*1024 + blk*16 + j])
// grid = 64(blk) * 4(g) * 16(kt); block = 256 (tx=j 0..15, ty=k16 0..15)
__global__ void prep_w_kernel(const float* __restrict__ W) {
    __shared__ float sm[16][17];
    int bx = blockIdx.x;
    int kt  = bx & 15;
    int g   = (bx >> 4) & 3;
    int blk = bx >> 6;
    int tx = threadIdx.x & 15;
    int ty = threadIdx.x >> 4;
    int col0 = g * HSZ + blk * 16;

    for (int kk = 0; kk < 4; kk++) {
        int k = kt * 64 + kk * 16;
        sm[ty][tx] = __uint_as_float(tf32r(W[(size_t)(FSZ + k + ty) * N4H + col0 + tx]));
        __syncthreads();
        g_Wr[((size_t)blk * MT + g * 16 + ty) * HSZ + k + tx] = sm[tx][ty];
        __syncthreads();
    }
}

// ---------------- precompute Z = X @ Wx + b (fp32 SIMT) ----------------
__global__ __launch_bounds__(256, 2)
void precompute_kernel(const float* __restrict__ X, const float* __restrict__ W,
                       const float* __restrict__ bias) {
    __shared__ float As[32][129];
    __shared__ float Bs[32][64];

    const int tid = threadIdx.x;
    const int tx = tid & 15;
    const int ty = tid >> 4;
    const int m0 = blockIdx.y * 128;
    const int n0 = blockIdx.x * 64;

    float acc[8][4];
#pragma unroll
    for (int r = 0; r < 8; r++)
#pragma unroll
        for (int c = 0; c < 4; c++) acc[r][c] = 0.0f;

    for (int k0 = 0; k0 < FSZ; k0 += 32) {
#pragma unroll
        for (int i = 0; i < 4; i++) {
            int li = tid + i * 256;
            int row = li >> 3;
            int kq  = (li & 7) << 2;
            float4 v = *(const float4*)(X + (size_t)(m0 + row) * FSZ + k0 + kq);
            As[kq + 0][row] = v.x; As[kq + 1][row] = v.y;
            As[kq + 2][row] = v.z; As[kq + 3][row] = v.w;
        }
#pragma unroll
        for (int i = 0; i < 2; i++) {
            int li = tid + i * 256;
            int kk = li >> 4;
            int cq = (li & 15) << 2;
            float4 v = *(const float4*)(W + (size_t)(k0 + kk) * N4H + n0 + cq);
            *(float4*)&Bs[kk][cq] = v;
        }
        __syncthreads();
#pragma unroll
        for (int kk = 0; kk < 32; kk++) {
            float a_frag[8], b_frag[4];
#pragma unroll
            for (int r = 0; r < 8; r++) a_frag[r] = As[kk][ty * 8 + r];
#pragma unroll
            for (int c = 0; c < 4; c++) b_frag[c] = Bs[kk][tx * 4 + c];
#pragma unroll
            for (int r = 0; r < 8; r++)
#pragma unroll
                for (int c = 0; c < 4; c++) acc[r][c] += a_frag[r] * b_frag[c];
        }
        __syncthreads();
    }
#pragma unroll
    for (int r = 0; r < 8; r++) {
        int m = m0 + ty * 8 + r;
        int t = m & (TSTEPS - 1);
        int bb = m >> 7;
        float* zr = g_Z + ((size_t)t * BSZ + bb) * N4H;
#pragma unroll
        for (int c = 0; c < 4; c++) {
            int n = n0 + tx * 4 + c;
            zr[n] = acc[r][c] + bias[n];
        }
    }
}

// ---------------- fused recurrent step: mma.sync tf32 + gate epilogue ----------------
// grid=64, block=256 (8 warps, 4(M) x 2(N) warp grid, warp tile 16x32)
// CTA blk: D[m=64 gate-rows][n=64 batch] = Wr_blk[64][1024] @ h[64][1024]^T
__global__ __launch_bounds__(256, 1)
void step_mma_kernel(float* __restrict__ d_out, int t, int p) {
    extern __shared__ char dsm_raw[];
    const uint32_t raw_base = smem_u32(dsm_raw);
    const uint32_t base     = (raw_base + 1023) & ~1023u;
    float* S = (float*)(dsm_raw + (base - raw_base));     // epilogue staging (reuses stage 0)

    const int tid  = threadIdx.x;
    const int wid  = tid >> 5;
    const int lane = tid & 31;
    const int blk  = blockIdx.x;
    const int wm   = wid >> 1;           // 0..3 (M warp)
    const int wn   = wid & 1;            // 0..1 (N warp)

    const float* __restrict__ hi = g_h[p];
    float* __restrict__ ho = g_h[p ^ 1];
    const float* __restrict__ wsrc = g_Wr + (size_t)blk * MT * HSZ;

    // ldmatrix address components (lane-dependent)
    const int grp = lane >> 3;
    const int r_l = lane & 7;
    const int a_row  = wm * 16 + ((grp & 1) << 3) + r_l;
    const int a_cko  = grp >> 1;
    const int b_row0 = wn * 32 + ((grp >> 1) << 3) + r_l;
    const int b_row1 = b_row0 + 16;
    const int b_cko  = grp & 1;

    float c[4][4];
#pragma unroll
    for (int j = 0; j < 4; j++)
#pragma unroll
        for (int q = 0; q < 4; q++) c[j][q] = 0.0f;

    // ---- async load of one k-tile into stage s ----
    auto load_tile = [&](int kt, int s) {
        const uint32_t aB = base + s * STAGE_BYTES;
        const uint32_t bB = aB + A_TILE_BYTES;
        const int k0 = kt * KT;
#pragma unroll
        for (int i = 0; i < 4; i++) {
            int id = tid + i * 256;           // 0..1023
            int row = id >> 4;
            int ck  = id & 15;
            const float* src = wsrc + (size_t)row * HSZ + k0 + ck * 4;
            uint32_t dst = aB + row * 256 + (((uint32_t)ck ^ (row & 7)) << 4);
            CP16(dst, src);
        }
#pragma unroll
        for (int i = 0; i < 4; i++) {
            int id = tid + i * 256;
            int row = id >> 4;
            int ck  = id & 15;
            const float* src = hi + (size_t)row * HSZ + k0 + ck * 4;
            uint32_t dst = bB + row * 256 + (((uint32_t)ck ^ (row & 7)) << 4);
            CP16(dst, src);
        }
    };

    load_tile(0, 0);
    CP_COMMIT();

    for (int kt = 0; kt < NKT; kt++) {
        if (kt + 1 < NKT) {
            load_tile(kt + 1, (kt + 1) & 1);
            CP_COMMIT();
            CP_WAIT1();
        } else {
            CP_WAIT0();
        }
        __syncthreads();

        const uint32_t aB = base + (kt & 1) * STAGE_BYTES;
        const uint32_t bB = aB + A_TILE_BYTES;
#pragma unroll
        for (int ks = 0; ks < KT / 8; ks++) {
            uint32_t a0, a1, a2, a3;
            uint32_t aAddr = aB + a_row * 256 + (((uint32_t)(ks * 2 + a_cko) ^ (a_row & 7)) << 4);
            LDSM_X4(a0, a1, a2, a3, aAddr);

            uint32_t b00, b01, b10, b11, b20, b21, b30, b31;
            uint32_t bAddr0 = bB + b_row0 * 256 + (((uint32_t)(ks * 2 + b_cko) ^ (b_row0 & 7)) << 4);
            LDSM_X4(b00, b01, b10, b11, bAddr0);
            uint32_t bAddr1 = bB + b_row1 * 256 + (((uint32_t)(ks * 2 + b_cko) ^ (b_row1 & 7)) << 4);
            LDSM_X4(b20, b21, b30, b31, bAddr1);

            MMA_TF32(c[0], a0, a1, a2, a3, b00, b01);
            MMA_TF32(c[1], a0, a1, a2, a3, b10, b11);
            MMA_TF32(c[2], a0, a1, a2, a3, b20, b21);
            MMA_TF32(c[3], a0, a1, a2, a3, b30, b31);
        }
        __syncthreads();
    }

    // ---- stash D tile into smem: S[m][n], stride 65 ----
    {
        const int gr = lane >> 2;
        const int qc = lane & 3;
#pragma unroll
        for (int j = 0; j < 4; j++) {
            int n = wn * 32 + j * 8 + 2 * qc;
            int m = wm * 16 + gr;
            S[m * 65 + n]           = c[j][0];
            S[m * 65 + n + 1]       = c[j][1];
            S[(m + 8) * 65 + n]     = c[j][2];
            S[(m + 8) * 65 + n + 1] = c[j][3];
        }
    }
    __syncthreads();

    // ---- gate epilogue: 16 hcols x 64 batch = 1024 cells, 4 per thread ----
    const float* zt = g_Z + (size_t)t * BSZ * N4H;
#pragma unroll
    for (int i = 0; i < 4; i++) {
        int cell = tid + i * 256;
        int j = cell & 15;            // local hcol
        int b = cell >> 4;            // batch
        int hcol = blk * 16 + j;
        const float* zrow = zt + (size_t)b * N4H;

        float zi = S[(0 * 16 + j) * 65 + b] + zrow[0 * HSZ + hcol];
        float zj = S[(1 * 16 + j) * 65 + b] + zrow[1 * HSZ + hcol];
        float zf = S[(2 * 16 + j) * 65 + b] + zrow[2 * HSZ + hcol];
        float zo = S[(3 * 16 + j) * 65 + b] + zrow[3 * HSZ + hcol];

        float c_old = g_c[(size_t)b * HSZ + hcol];
        float si = 1.0f / (1.0f + __expf(-zi));
        float sf = 1.0f / (1.0f + __expf(-(zf + 1.0f)));   // forget bias = 1.0
        float so = 1.0f / (1.0f + __expf(-zo));
        float tj = tanhf(zj);

        float c_new = c_old * sf + si * tj;
        float h_new = tanhf(c_new) * so;

        g_c[(size_t)b * HSZ + hcol] = c_new;
        ho[(size_t)b * HSZ + hcol]  = h_new;
        d_out[((size_t)b * TSTEPS + t) * HSZ + hcol] = h_new;
    }
}

// ---------------- launcher ----------------
extern "C" void kernel_launch(void* const* d_in, const int* in_sizes, int n_in,
                              void* d_out, int out_size) {
    const float* x = (const float*)d_in[0];   // [B, T, F]
    const float* W = (const float*)d_in[1];   // [F+H, 4H]
    const float* b = (const float*)d_in[2];   // [4H]
    float* out = (float*)d_out;               // [B, T, H]

    static bool attr_done = false;
    if (!attr_done) {
        cudaFuncSetAttribute(step_mma_kernel, cudaFuncAttributeMaxDynamicSharedMemorySize, DSMEM_BYTES);
        attr_done = true;
    }

    init_state_kernel<<<(BSZ * HSZ + 255) / 256, 256>>>();
    prep_w_kernel<<<64 * 4 * 16, 256>>>(W);
    {
        dim3 grid(N4H / 64, (BSZ * TSTEPS) / 128);
        precompute_kernel<<<grid, 256>>>(x, W, b);
    }
    for (int t = 0; t < TSTEPS; t++) {
        step_mma_kernel<<<NCTA, 256, DSMEM_BYTES>>>(out, t, t & 1);
    }
}

// round 4
// speedup vs baseline: 2.0597x; 1.2050x over previous
#include <cuda_runtime.h>
#include <cstdint>
#include <math.h>

// Problem constants
#define TSTEPS 128
#define BSZ    64
#define FSZ    1024
#define HSZ    1024
#define N4H    4096   // 4*H

// Persistent step-GEMM tiling
#define NCTA   128         // CTAs; each owns 8 hcols x 4 gates = 32 gate-rows (M=32)
#define MT     32
#define KT     64
#define NKT    (HSZ / KT)  // 16
#define A_SMEM_BYTES  131072            // 32 rows x 1024 f32 (swizzled, resident)
#define B_TILE_BYTES  16384             // 64 x 64 f32
#define DSMEM_BYTES   (A_SMEM_BYTES + 2 * B_TILE_BYTES + 1024)

// ---------------- device scratch ----------------
__device__ float g_Z[(size_t)TSTEPS * BSZ * N4H];    // [T][B][4H] precomputed x@Wx + b (128 MB)
__device__ float g_Wr[(size_t)NCTA * MT * HSZ];      // [blk][m][k] tf32-rounded recurrent weights
__device__ float g_h[2][BSZ * HSZ];                  // ping-pong hidden state
__device__ unsigned g_bar_count = 0;
__device__ volatile unsigned g_bar_gen = 0;

// ---------------- helpers ----------------
__device__ __forceinline__ uint32_t smem_u32(const void* p) {
    uint32_t a;
    asm("{ .reg .u64 t; cvta.to.shared.u64 t, %1; cvt.u32.u64 %0, t; }" : "=r"(a) : "l"(p));
    return a;
}
__device__ __forceinline__ uint32_t tf32r(float v) {
    uint32_t o;
    asm("cvt.rna.tf32.f32 %0, %1;" : "=r"(o) : "f"(v));
    return o;
}
#define CP16(dst, src) \
    asm volatile("cp.async.cg.shared.global [%0], [%1], 16;" :: "r"(dst), "l"(src) : "memory")
#define CP_COMMIT() asm volatile("cp.async.commit_group;" ::: "memory")
#define CP_WAIT1()  asm volatile("cp.async.wait_group 1;" ::: "memory")
#define CP_WAIT0()  asm volatile("cp.async.wait_group 0;" ::: "memory")

#define LDSM_X4(r0, r1, r2, r3, addr) \
    asm volatile("ldmatrix.sync.aligned.m8n8.x4.shared.b16 {%0,%1,%2,%3}, [%4];" \
                 : "=r"(r0), "=r"(r1), "=r"(r2), "=r"(r3) : "r"(addr))

#define MMA_TF32(c, a0, a1, a2, a3, b0, b1) \
    asm volatile("mma.sync.aligned.m16n8k8.row.col.f32.tf32.tf32.f32 " \
                 "{%0,%1,%2,%3}, {%4,%5,%6,%7}, {%8,%9}, {%0,%1,%2,%3};" \
                 : "+f"((c)[0]), "+f"((c)[1]), "+f"((c)[2]), "+f"((c)[3]) \
                 : "r"(a0), "r"(a1), "r"(a2), "r"(a3), "r"(b0), "r"(b1))

// ---------------- init: zero h[0] ----------------
__global__ void init_state_kernel() {
    int i = blockIdx.x * blockDim.x + threadIdx.x;
    if (i < BSZ * HSZ) { g_h[0][i] = 0.0f; }
}

// ---------------- prep: transpose recurrent weights into [blk][m=g*8+j][k], tf32-rounded ----------------
// grid = 128(blk) * 4(g) * 32(kt), block = 256
__global__ void prep_w_kernel(const float* __restrict__ W) {
    __shared__ float sm[32][9];
    int bx  = blockIdx.x;
    int kt  = bx & 31;
    int g   = (bx >> 5) & 3;
    int blk = bx >> 7;
    int tid = threadIdx.x;

    int jx = tid & 7;
    int ky = tid >> 3;           // 0..31
    sm[ky][jx] = W[(size_t)(FSZ + kt * 32 + ky) * N4H + g * HSZ + blk * 8 + jx];
    __syncthreads();

    int k2 = tid & 31;
    int j2 = tid >> 5;           // 0..7
    g_Wr[((size_t)blk * MT + g * 8 + j2) * HSZ + kt * 32 + k2] =
        __uint_as_float(tf32r(sm[k2][j2]));
}

// ---------------- precompute Z = X @ Wx + b (fp32 SIMT) ----------------
__global__ __launch_bounds__(256, 2)
void precompute_kernel(const float* __restrict__ X, const float* __restrict__ W,
                       const float* __restrict__ bias) {
    __shared__ float As[32][129];
    __shared__ float Bs[32][64];

    const int tid = threadIdx.x;
    const int tx = tid & 15;
    const int ty = tid >> 4;
    const int m0 = blockIdx.y * 128;
    const int n0 = blockIdx.x * 64;

    float acc[8][4];
#pragma unroll
    for (int r = 0; r < 8; r++)
#pragma unroll
        for (int c = 0; c < 4; c++) acc[r][c] = 0.0f;

    for (int k0 = 0; k0 < FSZ; k0 += 32) {
#pragma unroll
        for (int i = 0; i < 4; i++) {
            int li = tid + i * 256;
            int row = li >> 3;
            int kq  = (li & 7) << 2;
            float4 v = *(const float4*)(X + (size_t)(m0 + row) * FSZ + k0 + kq);
            As[kq + 0][row] = v.x; As[kq + 1][row] = v.y;
            As[kq + 2][row] = v.z; As[kq + 3][row] = v.w;
        }
#pragma unroll
        for (int i = 0; i < 2; i++) {
            int li = tid + i * 256;
            int kk = li >> 4;
            int cq = (li & 15) << 2;
            float4 v = *(const float4*)(W + (size_t)(k0 + kk) * N4H + n0 + cq);
            *(float4*)&Bs[kk][cq] = v;
        }
        __syncthreads();
#pragma unroll
        for (int kk = 0; kk < 32; kk++) {
            float a_frag[8], b_frag[4];
#pragma unroll
            for (int r = 0; r < 8; r++) a_frag[r] = As[kk][ty * 8 + r];
#pragma unroll
            for (int c = 0; c < 4; c++) b_frag[c] = Bs[kk][tx * 4 + c];
#pragma unroll
            for (int r = 0; r < 8; r++)
#pragma unroll
                for (int c = 0; c < 4; c++) acc[r][c] += a_frag[r] * b_frag[c];
        }
        __syncthreads();
    }
#pragma unroll
    for (int r = 0; r < 8; r++) {
        int m = m0 + ty * 8 + r;
        int t = m & (TSTEPS - 1);
        int bb = m >> 7;
        float* zr = g_Z + ((size_t)t * BSZ + bb) * N4H;
#pragma unroll
        for (int c = 0; c < 4; c++) {
            int n = n0 + tx * 4 + c;
            zr[n] = acc[r][c] + bias[n];
        }
    }
}

// ---------------- grid-wide barrier (all NCTA CTAs resident) ----------------
__device__ __forceinline__ void grid_barrier() {
    __threadfence();
    __syncthreads();
    if (threadIdx.x == 0) {
        unsigned gen = g_bar_gen;
        if (atomicAdd(&g_bar_count, 1u) == NCTA - 1) {
            g_bar_count = 0;
            __threadfence();
            g_bar_gen = gen + 1;
        } else {
            while (g_bar_gen == gen) { }
        }
    }
    __syncthreads();
}

// ---------------- persistent LSTM kernel ----------------
// grid=128, block=256 (8 warps: wm = wid>>2 in 0..1 (m16), wn = wid&3 in 0..3 (n16))
// CTA blk: each step D[32 gate-rows][64 batch] = Wsm[32][1024] @ h[64][1024]^T
__global__ __launch_bounds__(256, 1)
void lstm_persist_kernel(float* __restrict__ d_out) {
    extern __shared__ char dsm_raw[];
    __shared__ float c_sm[BSZ * 8];     // cell state, [b*8 + j]

    const uint32_t raw_base = smem_u32(dsm_raw);
    const uint32_t base     = (raw_base + 1023) & ~1023u;
    const uint32_t aS       = base;                      // A panel (resident)
    const uint32_t bS0      = base + A_SMEM_BYTES;       // B stage 0
    float* S = (float*)(dsm_raw + (bS0 - raw_base));     // epilogue staging overlays stage 0

    const int tid  = threadIdx.x;
    const int wid  = tid >> 5;
    const int lane = tid & 31;
    const int blk  = blockIdx.x;
    const int wm   = wid >> 2;          // 0..1
    const int wn   = wid & 3;           // 0..3

    // zero cell state
    c_sm[tid] = 0.0f;
    c_sm[tid + 256] = 0.0f;

    // ---- load resident A panel (32 x 1024 f32, swizzled) ----
    {
        const float* wsrc = g_Wr + (size_t)blk * MT * HSZ;
#pragma unroll
        for (int i = 0; i < 32; i++) {
            int u = tid + i * 256;          // 16B unit index, 0..8191
            int m  = u >> 8;
            int ck = u & 255;
            uint32_t dst = aS + m * 4096 + (((uint32_t)ck ^ (m & 7)) << 4);
            CP16(dst, wsrc + (size_t)u * 4);
        }
        CP_COMMIT();
        CP_WAIT0();
    }
    __syncthreads();

    // lane-dependent ldmatrix address components
    const int grp = lane >> 3;
    const int r_l = lane & 7;
    const int a_row  = wm * 16 + ((grp & 1) << 3) + r_l;
    const int a_cko  = grp >> 1;
    const int b_row  = wn * 16 + ((grp >> 1) << 3) + r_l;
    const int b_cko  = grp & 1;
    const uint32_t aRowBase = aS + a_row * 4096;

    for (int t = 0; t < TSTEPS; t++) {
        const float* __restrict__ hi = g_h[t & 1];
        float* __restrict__ ho = g_h[(t + 1) & 1];

        float c[2][4];
#pragma unroll
        for (int j = 0; j < 2; j++)
#pragma unroll
            for (int q = 0; q < 4; q++) c[j][q] = 0.0f;

        // prefetch B tile 0
        {
            const uint32_t bB = bS0;
#pragma unroll
            for (int i = 0; i < 4; i++) {
                int id = tid + i * 256;
                int row = id >> 4;
                int ck  = id & 15;
                CP16(bB + row * 256 + (((uint32_t)ck ^ (row & 7)) << 4),
                     hi + (size_t)row * HSZ + ck * 4);
            }
            CP_COMMIT();
        }

        for (int kt = 0; kt < NKT; kt++) {
            if (kt + 1 < NKT) {
                const uint32_t bB = bS0 + ((kt + 1) & 1) * B_TILE_BYTES;
                const int k0 = (kt + 1) * KT;
#pragma unroll
                for (int i = 0; i < 4; i++) {
                    int id = tid + i * 256;
                    int row = id >> 4;
                    int ck  = id & 15;
                    CP16(bB + row * 256 + (((uint32_t)ck ^ (row & 7)) << 4),
                         hi + (size_t)row * HSZ + k0 + ck * 4);
                }
                CP_COMMIT();
                CP_WAIT1();
            } else {
                CP_WAIT0();
            }
            __syncthreads();

            const uint32_t bB = bS0 + (kt & 1) * B_TILE_BYTES;
#pragma unroll
            for (int ks = 0; ks < KT / 8; ks++) {
                uint32_t a0, a1, a2, a3;
                uint32_t aAddr = aRowBase +
                    (((uint32_t)(kt * 16 + ks * 2 + a_cko) ^ (a_row & 7)) << 4);
                LDSM_X4(a0, a1, a2, a3, aAddr);

                uint32_t b00, b01, b10, b11;
                uint32_t bAddr = bB + b_row * 256 +
                    (((uint32_t)(ks * 2 + b_cko) ^ (b_row & 7)) << 4);
                LDSM_X4(b00, b01, b10, b11, bAddr);

                MMA_TF32(c[0], a0, a1, a2, a3, b00, b01);
                MMA_TF32(c[1], a0, a1, a2, a3, b10, b11);
            }
            __syncthreads();
        }

        // ---- stash D tile into smem: S[m][n], stride 65 ----
        {
            const int gr = lane >> 2;
            const int qc = lane & 3;
#pragma unroll
            for (int j = 0; j < 2; j++) {
                int n = wn * 16 + j * 8 + 2 * qc;
                int m = wm * 16 + gr;
                S[m * 65 + n]           = c[j][0];
                S[m * 65 + n + 1]       = c[j][1];
                S[(m + 8) * 65 + n]     = c[j][2];
                S[(m + 8) * 65 + n + 1] = c[j][3];
            }
        }
        __syncthreads();

        // ---- gate epilogue: 8 hcols x 64 batch = 512 cells, 2 per thread ----
        const float* zt = g_Z + (size_t)t * BSZ * N4H;
#pragma unroll
        for (int i = 0; i < 2; i++) {
            int cell = tid + i * 256;
            int j = cell & 7;
            int b = cell >> 3;
            int hcol = blk * 8 + j;
            const float* zrow = zt + (size_t)b * N4H;

            float zi = S[(0 * 8 + j) * 65 + b] + zrow[0 * HSZ + hcol];
            float zj = S[(1 * 8 + j) * 65 + b] + zrow[1 * HSZ + hcol];
            float zf = S[(2 * 8 + j) * 65 + b] + zrow[2 * HSZ + hcol];
            float zo = S[(3 * 8 + j) * 65 + b] + zrow[3 * HSZ + hcol];

            float c_old = c_sm[cell];
            float si = 1.0f / (1.0f + __expf(-zi));
            float sf = 1.0f / (1.0f + __expf(-(zf + 1.0f)));   // forget bias = 1.0
            float so = 1.0f / (1.0f + __expf(-zo));
            float tj = tanhf(zj);

            float c_new = c_old * sf + si * tj;
            float h_new = tanhf(c_new) * so;

            c_sm[cell] = c_new;
            ho[(size_t)b * HSZ + hcol] = h_new;
            d_out[((size_t)b * TSTEPS + t) * HSZ + hcol] = h_new;
        }

        grid_barrier();
    }
}

// ---------------- launcher ----------------
extern "C" void kernel_launch(void* const* d_in, const int* in_sizes, int n_in,
                              void* d_out, int out_size) {
    const float* x = (const float*)d_in[0];   // [B, T, F]
    const float* W = (const float*)d_in[1];   // [F+H, 4H]
    const float* b = (const float*)d_in[2];   // [4H]
    float* out = (float*)d_out;               // [B, T, H]

    static bool attr_done = false;
    if (!attr_done) {
        cudaFuncSetAttribute(lstm_persist_kernel, cudaFuncAttributeMaxDynamicSharedMemorySize,
                             DSMEM_BYTES);
        attr_done = true;
    }

    init_state_kernel<<<(BSZ * HSZ + 255) / 256, 256>>>();
    prep_w_kernel<<<NCTA * 4 * 32, 256>>>(W);
    {
        dim3 grid(N4H / 64, (BSZ * TSTEPS) / 128);
        precompute_kernel<<<grid, 256>>>(x, W, b);
    }
    lstm_persist_kernel<<<NCTA, 256, DSMEM_BYTES>>>(out);
}

// round 5
// speedup vs baseline: 3.4810x; 1.6901x over previous
#include <cuda_runtime.h>
#include <cstdint>
#include <math.h>

// Problem constants
#define TSTEPS 128
#define BSZ    64
#define FSZ    1024
#define HSZ    1024
#define N4H    4096   // 4*H

// Persistent step-GEMM tiling
#define NCTA   128         // CTAs; each owns 8 hcols x 4 gates = 32 gate-rows (M=32)
#define MT     32
#define KT     64
#define A_SMEM_BYTES  131072            // 32 rows x 1024 f32 (swizzled, resident)
#define B_TILE_BYTES  16384             // 64 x 64 f32
#define DSMEM_BYTES   (A_SMEM_BYTES + 4 * B_TILE_BYTES + 1024)   // 197632

// Precompute GEMM (tf32 MMA): M=8192 (b*T rows of x), N=4096, K=1024
#define PC_STAGE_BYTES 32768
#define PC_DSMEM (2 * PC_STAGE_BYTES + 1024)

// ---------------- device scratch ----------------
__device__ float g_Z[(size_t)TSTEPS * BSZ * N4H];    // [T][B][4H] precomputed x@Wx + b (128 MB)
__device__ float g_Wr[(size_t)NCTA * MT * HSZ];      // [blk][m][k] tf32-rounded recurrent weights
__device__ float g_Wxt[(size_t)N4H * FSZ];           // [n][k] tf32-rounded input weights (transposed)
__device__ float g_h[2][BSZ * HSZ];                  // ping-pong hidden state
__device__ unsigned g_bar_count = 0;
__device__ volatile unsigned g_bar_gen = 0;

// ---------------- helpers ----------------
__device__ __forceinline__ uint32_t smem_u32(const void* p) {
    uint32_t a;
    asm("{ .reg .u64 t; cvta.to.shared.u64 t, %1; cvt.u32.u64 %0, t; }" : "=r"(a) : "l"(p));
    return a;
}
__device__ __forceinline__ uint32_t tf32r(float v) {
    uint32_t o;
    asm("cvt.rna.tf32.f32 %0, %1;" : "=r"(o) : "f"(v));
    return o;
}
#define CP16(dst, src) \
    asm volatile("cp.async.cg.shared.global [%0], [%1], 16;" :: "r"(dst), "l"(src) : "memory")
#define CP_COMMIT() asm volatile("cp.async.commit_group;" ::: "memory")
#define CP_WAIT1()  asm volatile("cp.async.wait_group 1;" ::: "memory")
#define CP_WAIT0()  asm volatile("cp.async.wait_group 0;" ::: "memory")

#define LDSM_X4(r0, r1, r2, r3, addr) \
    asm volatile("ldmatrix.sync.aligned.m8n8.x4.shared.b16 {%0,%1,%2,%3}, [%4];" \
                 : "=r"(r0), "=r"(r1), "=r"(r2), "=r"(r3) : "r"(addr))

#define MMA_TF32(c, a0, a1, a2, a3, b0, b1) \
    asm volatile("mma.sync.aligned.m16n8k8.row.col.f32.tf32.tf32.f32 " \
                 "{%0,%1,%2,%3}, {%4,%5,%6,%7}, {%8,%9}, {%0,%1,%2,%3};" \
                 : "+f"((c)[0]), "+f"((c)[1]), "+f"((c)[2]), "+f"((c)[3]) \
                 : "r"(a0), "r"(a1), "r"(a2), "r"(a3), "r"(b0), "r"(b1))

// ---------------- init: zero h[0] ----------------
__global__ void init_state_kernel() {
    int i = blockIdx.x * blockDim.x + threadIdx.x;
    if (i < BSZ * HSZ) { g_h[0][i] = 0.0f; }
}

// ---------------- prep: recurrent weights -> [blk][m=g*8+j][k], tf32-rounded ----------------
__global__ void prep_w_kernel(const float* __restrict__ W) {
    __shared__ float sm[32][9];
    int bx  = blockIdx.x;
    int kt  = bx & 31;
    int g   = (bx >> 5) & 3;
    int blk = bx >> 7;
    int tid = threadIdx.x;

    int jx = tid & 7;
    int ky = tid >> 3;
    sm[ky][jx] = W[(size_t)(FSZ + kt * 32 + ky) * N4H + g * HSZ + blk * 8 + jx];
    __syncthreads();

    int k2 = tid & 31;
    int j2 = tid >> 5;
    g_Wr[((size_t)blk * MT + g * 8 + j2) * HSZ + kt * 32 + k2] =
        __uint_as_float(tf32r(sm[k2][j2]));
}

// ---------------- prep: transpose input weights W[0:F][4H] -> g_Wxt[n][k], tf32-rounded ----------------
// grid = (FSZ/32, N4H/32), block = 256
__global__ void prep_wxt_kernel(const float* __restrict__ W) {
    __shared__ float sm[32][33];
    int k0 = blockIdx.x * 32;
    int n0 = blockIdx.y * 32;
    int tx = threadIdx.x & 31;
    int ty = threadIdx.x >> 5;         // 0..7
#pragma unroll
    for (int r = 0; r < 4; r++) {
        int row = ty + r * 8;
        sm[row][tx] = W[(size_t)(k0 + row) * N4H + n0 + tx];
    }
    __syncthreads();
#pragma unroll
    for (int r = 0; r < 4; r++) {
        int row = ty + r * 8;
        g_Wxt[(size_t)(n0 + row) * FSZ + k0 + tx] = __uint_as_float(tf32r(sm[tx][row]));
    }
}

// ---------------- precompute Z = X @ Wx + b (tf32 mma.sync) ----------------
// grid = (64 n-tiles, 128 m-tiles), block=256 (8 warps, 4(M)x2(N), warp tile 16x32)
__global__ __launch_bounds__(256, 2)
void precompute_mma_kernel(const float* __restrict__ X, const float* __restrict__ bias,
                           float* __restrict__ Z) {
    extern __shared__ char dsm_raw[];
    const uint32_t raw_base = smem_u32(dsm_raw);
    const uint32_t base     = (raw_base + 1023) & ~1023u;

    const int tid  = threadIdx.x;
    const int wid  = tid >> 5;
    const int lane = tid & 31;
    const int wm   = wid >> 1;          // 0..3
    const int wn   = wid & 1;           // 0..1
    const int n0   = blockIdx.x * 64;
    const int m0   = blockIdx.y * 64;

    const int grp = lane >> 3;
    const int r_l = lane & 7;
    const int a_row  = wm * 16 + ((grp & 1) << 3) + r_l;
    const int a_cko  = grp >> 1;
    const int b_row0 = wn * 32 + ((grp >> 1) << 3) + r_l;
    const int b_row1 = b_row0 + 16;
    const int b_cko  = grp & 1;

    float c[4][4];
#pragma unroll
    for (int j = 0; j < 4; j++)
#pragma unroll
        for (int q = 0; q < 4; q++) c[j][q] = 0.0f;

    auto load_tile = [&](int kt, int s) {
        const uint32_t aB = base + s * PC_STAGE_BYTES;
        const uint32_t bB = aB + 16384;
        const int k0 = kt * KT;
#pragma unroll
        for (int i = 0; i < 4; i++) {
            int id = tid + i * 256;
            int row = id >> 4;
            int ck  = id & 15;
            CP16(aB + row * 256 + (((uint32_t)ck ^ (row & 7)) << 4),
                 X + (size_t)(m0 + row) * FSZ + k0 + ck * 4);
        }
#pragma unroll
        for (int i = 0; i < 4; i++) {
            int id = tid + i * 256;
            int row = id >> 4;
            int ck  = id & 15;
            CP16(bB + row * 256 + (((uint32_t)ck ^ (row & 7)) << 4),
                 g_Wxt + (size_t)(n0 + row) * FSZ + k0 + ck * 4);
        }
    };

    load_tile(0, 0);
    CP_COMMIT();

    for (int kt = 0; kt < FSZ / KT; kt++) {
        if (kt + 1 < FSZ / KT) {
            load_tile(kt + 1, (kt + 1) & 1);
            CP_COMMIT();
            CP_WAIT1();
        } else {
            CP_WAIT0();
        }
        __syncthreads();

        const uint32_t aB = base + (kt & 1) * PC_STAGE_BYTES;
        const uint32_t bB = aB + 16384;
#pragma unroll
        for (int ks = 0; ks < KT / 8; ks++) {
            uint32_t a0, a1, a2, a3;
            uint32_t aAddr = aB + a_row * 256 + (((uint32_t)(ks * 2 + a_cko) ^ (a_row & 7)) << 4);
            LDSM_X4(a0, a1, a2, a3, aAddr);
            uint32_t b00, b01, b10, b11, b20, b21, b30, b31;
            uint32_t bAddr0 = bB + b_row0 * 256 + (((uint32_t)(ks * 2 + b_cko) ^ (b_row0 & 7)) << 4);
            LDSM_X4(b00, b01, b10, b11, bAddr0);
            uint32_t bAddr1 = bB + b_row1 * 256 + (((uint32_t)(ks * 2 + b_cko) ^ (b_row1 & 7)) << 4);
            LDSM_X4(b20, b21, b30, b31, bAddr1);

            MMA_TF32(c[0], a0, a1, a2, a3, b00, b01);
            MMA_TF32(c[1], a0, a1, a2, a3, b10, b11);
            MMA_TF32(c[2], a0, a1, a2, a3, b20, b21);
            MMA_TF32(c[3], a0, a1, a2, a3, b30, b31);
        }
        __syncthreads();
    }

    // epilogue: add bias, write to Z[t][b][n]; m -> (b = m>>7, t = m&127)
    const int gr = lane >> 2;
    const int qc = lane & 3;
#pragma unroll
    for (int j = 0; j < 4; j++) {
        int n = n0 + wn * 32 + j * 8 + 2 * qc;
        float2 bia = *(const float2*)(bias + n);
        int m1 = m0 + wm * 16 + gr;
        int m2 = m1 + 8;
        float2 v1 = { c[j][0] + bia.x, c[j][1] + bia.y };
        float2 v2 = { c[j][2] + bia.x, c[j][3] + bia.y };
        *(float2*)(Z + ((size_t)(m1 & 127) * BSZ + (m1 >> 7)) * N4H + n) = v1;
        *(float2*)(Z + ((size_t)(m2 & 127) * BSZ + (m2 >> 7)) * N4H + n) = v2;
    }
}

// ---------------- persistent LSTM kernel ----------------
// grid=128, block=512. Warps 0-7: k in [0,512); warps 8-15: k in [512,1024).
// Per group: 8 warps (2x4 grid of 16x16 warp tiles) over D[32 gate-rows][64 batch].
__global__ __launch_bounds__(512, 1)
void lstm_persist_kernel(float* __restrict__ d_out) {
    extern __shared__ char dsm_raw[];
    __shared__ float c_sm[512];           // cell state [b*8 + j]
    __shared__ float Zs[4 * 512];         // Z staging [g][b*8+j]

    const uint32_t raw_base = smem_u32(dsm_raw);
    const uint32_t base     = (raw_base + 1023) & ~1023u;
    const uint32_t aS       = base;
    const uint32_t zsB      = smem_u32(Zs);
    float* Sf = (float*)(dsm_raw + (base - raw_base) + A_SMEM_BYTES);  // partials overlay B area

    const int tid  = threadIdx.x;
    const int wid  = tid >> 5;
    const int lane = tid & 31;
    const int blk  = blockIdx.x;
    const int kw   = wid >> 3;            // 0..1 k-split group
    const int wg   = wid & 7;
    const int wm   = wg >> 2;             // 0..1
    const int wn   = wg & 3;              // 0..3
    const int tig  = tid & 255;           // thread id within group

    c_sm[tid] = 0.0f;

    // ---- load resident A panel (32 x 1024 f32, swizzled) ----
    {
        const float* wsrc = g_Wr + (size_t)blk * MT * HSZ;
#pragma unroll
        for (int i = 0; i < 16; i++) {
            int u = tid + i * 512;
            int m  = u >> 8;
            int ck = u & 255;
            CP16(aS + m * 4096 + (((uint32_t)ck ^ (m & 7)) << 4), wsrc + (size_t)u * 4);
        }
        CP_COMMIT();
        CP_WAIT0();
    }
    __syncthreads();

    // lane-dependent ldmatrix address components
    const int grp = lane >> 3;
    const int r_l = lane & 7;
    const int a_row  = wm * 16 + ((grp & 1) << 3) + r_l;
    const int a_cko  = grp >> 1;
    const int b_row  = wn * 16 + ((grp >> 1) << 3) + r_l;
    const int b_cko  = grp & 1;
    const uint32_t aRowBase = aS + a_row * 4096;

    // epilogue indices
    const int e_j = tid & 7;
    const int e_b = tid >> 3;
    const int e_hcol = blk * 8 + e_j;

    for (int t = 0; t < TSTEPS; t++) {
        const float* __restrict__ hi = g_h[t & 1];
        float* __restrict__ ho = g_h[(t + 1) & 1];

        float c[2][4];
#pragma unroll
        for (int j = 0; j < 2; j++)
#pragma unroll
            for (int q = 0; q < 4; q++) c[j][q] = 0.0f;

        // prefetch Z(t) + B tile 0 (one group)
        {
            const float* zt = g_Z + (size_t)t * BSZ * N4H;
            int chunk = tid >> 1, half = tid & 1;
            int g = chunk & 3, b = chunk >> 2;
            CP16(zsB + ((uint32_t)(g * 512 + b * 8 + half * 4) << 2),
                 zt + (size_t)b * N4H + g * HSZ + blk * 8 + half * 4);

            const uint32_t bB = base + A_SMEM_BYTES + kw * 2 * B_TILE_BYTES;
            const int k0 = kw * 512;
#pragma unroll
            for (int i = 0; i < 4; i++) {
                int id = tig + i * 256;
                int row = id >> 4;
                int ck  = id & 15;
                CP16(bB + row * 256 + (((uint32_t)ck ^ (row & 7)) << 4),
                     hi + (size_t)row * HSZ + k0 + ck * 4);
            }
            CP_COMMIT();
        }

        for (int kt = 0; kt < 8; kt++) {
            if (kt + 1 < 8) {
                const uint32_t bB = base + A_SMEM_BYTES + kw * 2 * B_TILE_BYTES
                                  + ((kt + 1) & 1) * B_TILE_BYTES;
                const int k0 = kw * 512 + (kt + 1) * KT;
#pragma unroll
                for (int i = 0; i < 4; i++) {
                    int id = tig + i * 256;
                    int row = id >> 4;
                    int ck  = id & 15;
                    CP16(bB + row * 256 + (((uint32_t)ck ^ (row & 7)) << 4),
                         hi + (size_t)row * HSZ + k0 + ck * 4);
                }
                CP_COMMIT();
                CP_WAIT1();
            } else {
                CP_WAIT0();
            }
            __syncthreads();

            const uint32_t bB = base + A_SMEM_BYTES + kw * 2 * B_TILE_BYTES
                              + (kt & 1) * B_TILE_BYTES;
#pragma unroll
            for (int ks = 0; ks < KT / 8; ks++) {
                uint32_t a0, a1, a2, a3;
                uint32_t aAddr = aRowBase +
                    (((uint32_t)(kw * 128 + kt * 16 + ks * 2 + a_cko) ^ (a_row & 7)) << 4);
                LDSM_X4(a0, a1, a2, a3, aAddr);

                uint32_t b00, b01, b10, b11;
                uint32_t bAddr = bB + b_row * 256 +
                    (((uint32_t)(ks * 2 + b_cko) ^ (b_row & 7)) << 4);
                LDSM_X4(b00, b01, b10, b11, bAddr);

                MMA_TF32(c[0], a0, a1, a2, a3, b00, b01);
                MMA_TF32(c[1], a0, a1, a2, a3, b10, b11);
            }
            __syncthreads();
        }

        // ---- stash partials: S[kw][m][n], stride 65 ----
        {
            float* S = Sf + kw * (MT * 65);
            const int gr = lane >> 2;
            const int qc = lane & 3;
#pragma unroll
            for (int j = 0; j < 2; j++) {
                int n = wn * 16 + j * 8 + 2 * qc;
                int m = wm * 16 + gr;
                S[m * 65 + n]           = c[j][0];
                S[m * 65 + n + 1]       = c[j][1];
                S[(m + 8) * 65 + n]     = c[j][2];
                S[(m + 8) * 65 + n + 1] = c[j][3];
            }
        }
        __syncthreads();

        // ---- gate epilogue: 512 cells, 1 per thread ----
        float h_new;
        {
            float* S0 = Sf;
            float* S1 = Sf + MT * 65;
            float zi = S0[(0 * 8 + e_j) * 65 + e_b] + S1[(0 * 8 + e_j) * 65 + e_b] + Zs[0 * 512 + tid];
            float zj = S0[(1 * 8 + e_j) * 65 + e_b] + S1[(1 * 8 + e_j) * 65 + e_b] + Zs[1 * 512 + tid];
            float zf = S0[(2 * 8 + e_j) * 65 + e_b] + S1[(2 * 8 + e_j) * 65 + e_b] + Zs[2 * 512 + tid];
            float zo = S0[(3 * 8 + e_j) * 65 + e_b] + S1[(3 * 8 + e_j) * 65 + e_b] + Zs[3 * 512 + tid];

            float c_old = c_sm[tid];
            float si = 1.0f / (1.0f + __expf(-zi));
            float sf = 1.0f / (1.0f + __expf(-(zf + 1.0f)));   // forget bias = 1.0
            float so = 1.0f / (1.0f + __expf(-zo));
            float tj = tanhf(zj);

            float c_new = c_old * sf + si * tj;
            h_new = tanhf(c_new) * so;

            c_sm[tid] = c_new;
            ho[(size_t)e_b * HSZ + e_hcol] = h_new;
        }

        if (t == TSTEPS - 1) {
            d_out[((size_t)e_b * TSTEPS + t) * HSZ + e_hcol] = h_new;
            break;
        }

        // ---- grid barrier, with d_out store overlapped ----
        __threadfence();
        __syncthreads();
        unsigned gen = 0;
        if (tid == 0) {
            gen = g_bar_gen;
            if (atomicAdd(&g_bar_count, 1u) == NCTA - 1) {
                g_bar_count = 0;
                __threadfence();
                g_bar_gen = gen + 1;
            }
        }
        d_out[((size_t)e_b * TSTEPS + t) * HSZ + e_hcol] = h_new;
        if (tid == 0) {
            while (g_bar_gen == gen) { }
        }
        __syncthreads();
    }
}

// ---------------- launcher ----------------
extern "C" void kernel_launch(void* const* d_in, const int* in_sizes, int n_in,
                              void* d_out, int out_size) {
    const float* x = (const float*)d_in[0];   // [B, T, F]
    const float* W = (const float*)d_in[1];   // [F+H, 4H]
    const float* b = (const float*)d_in[2];   // [4H]
    float* out = (float*)d_out;               // [B, T, H]

    static bool attr_done = false;
    if (!attr_done) {
        cudaFuncSetAttribute(lstm_persist_kernel, cudaFuncAttributeMaxDynamicSharedMemorySize,
                             DSMEM_BYTES);
        cudaFuncSetAttribute(precompute_mma_kernel, cudaFuncAttributeMaxDynamicSharedMemorySize,
                             PC_DSMEM);
        attr_done = true;
    }

    float* zbuf;
    cudaGetSymbolAddress((void**)&zbuf, g_Z);

    init_state_kernel<<<(BSZ * HSZ + 255) / 256, 256>>>();
    prep_w_kernel<<<NCTA * 4 * 32, 256>>>(W);
    {
        dim3 g(FSZ / 32, N4H / 32);
        prep_wxt_kernel<<<g, 256>>>(W);
    }
    {
        dim3 g(N4H / 64, (BSZ * TSTEPS) / 64);   // (64, 128)
        precompute_mma_kernel<<<g, 256, PC_DSMEM>>>(x, b, zbuf);
    }
    lstm_persist_kernel<<<NCTA, 512, DSMEM_BYTES>>>(out);
}

// round 6
// speedup vs baseline: 4.0501x; 1.1635x over previous
#include <cuda_runtime.h>
#include <cstdint>
#include <math.h>

// Problem constants
#define TSTEPS 128
#define BSZ    64
#define FSZ    1024
#define HSZ    1024
#define N4H    4096   // 4*H

// Persistent step-GEMM tiling: 4 k-groups x 4 warps, warp tile 16x32, KT=32
#define NCTA   128
#define MT     32
#define A_SMEM_BYTES  131072            // 32 rows x 1024 f32 (swizzled, resident)
#define BG_BYTES      16384             // per-group B region: 2 stages x 8 KB
#define DSMEM_BYTES   (A_SMEM_BYTES + 4 * BG_BYTES + 1024)   // 197632

// Precompute GEMM: block tile 128x64, warp tile 32x32, KT=64
#define PC_STAGE_BYTES 49152            // A 32 KB + B 16 KB
#define PC_DSMEM (2 * PC_STAGE_BYTES + 1024)

// ---------------- device scratch ----------------
__device__ float g_Z[(size_t)TSTEPS * BSZ * N4H];    // [T][B][4H] precomputed x@Wx + b (128 MB)
__device__ float g_Wr[(size_t)NCTA * MT * HSZ];      // [blk][m][k] tf32-rounded recurrent weights
__device__ float g_Wxt[(size_t)N4H * FSZ];           // [n][k] tf32-rounded input weights (transposed)
__device__ float g_h[2][BSZ * HSZ];                  // ping-pong hidden state
__device__ unsigned g_bar_count = 0;
__device__ volatile unsigned g_bar_gen = 0;

// ---------------- helpers ----------------
__device__ __forceinline__ uint32_t smem_u32(const void* p) {
    uint32_t a;
    asm("{ .reg .u64 t; cvta.to.shared.u64 t, %1; cvt.u32.u64 %0, t; }" : "=r"(a) : "l"(p));
    return a;
}
__device__ __forceinline__ uint32_t tf32r(float v) {
    uint32_t o;
    asm("cvt.rna.tf32.f32 %0, %1;" : "=r"(o) : "f"(v));
    return o;
}
#define CP16(dst, src) \
    asm volatile("cp.async.cg.shared.global [%0], [%1], 16;" :: "r"(dst), "l"(src) : "memory")
#define CP_COMMIT() asm volatile("cp.async.commit_group;" ::: "memory")
#define CP_WAIT1()  asm volatile("cp.async.wait_group 1;" ::: "memory")
#define CP_WAIT0()  asm volatile("cp.async.wait_group 0;" ::: "memory")
#define BARG(id)    asm volatile("bar.sync %0, 128;" :: "r"(id) : "memory")

#define LDSM_X4(r0, r1, r2, r3, addr) \
    asm volatile("ldmatrix.sync.aligned.m8n8.x4.shared.b16 {%0,%1,%2,%3}, [%4];" \
                 : "=r"(r0), "=r"(r1), "=r"(r2), "=r"(r3) : "r"(addr))

#define MMA_TF32(c, a0, a1, a2, a3, b0, b1) \
    asm volatile("mma.sync.aligned.m16n8k8.row.col.f32.tf32.tf32.f32 " \
                 "{%0,%1,%2,%3}, {%4,%5,%6,%7}, {%8,%9}, {%0,%1,%2,%3};" \
                 : "+f"((c)[0]), "+f"((c)[1]), "+f"((c)[2]), "+f"((c)[3]) \
                 : "r"(a0), "r"(a1), "r"(a2), "r"(a3), "r"(b0), "r"(b1))

// ---------------- init: zero h[0] ----------------
__global__ void init_state_kernel() {
    int i = blockIdx.x * blockDim.x + threadIdx.x;
    if (i < BSZ * HSZ) { g_h[0][i] = 0.0f; }
}

// ---------------- prep: recurrent weights -> [blk][m=g*8+j][k], tf32-rounded ----------------
__global__ void prep_w_kernel(const float* __restrict__ W) {
    __shared__ float sm[32][9];
    int bx  = blockIdx.x;
    int kt  = bx & 31;
    int g   = (bx >> 5) & 3;
    int blk = bx >> 7;
    int tid = threadIdx.x;

    int jx = tid & 7;
    int ky = tid >> 3;
    sm[ky][jx] = W[(size_t)(FSZ + kt * 32 + ky) * N4H + g * HSZ + blk * 8 + jx];
    __syncthreads();

    int k2 = tid & 31;
    int j2 = tid >> 5;
    g_Wr[((size_t)blk * MT + g * 8 + j2) * HSZ + kt * 32 + k2] =
        __uint_as_float(tf32r(sm[k2][j2]));
}

// ---------------- prep: transpose W[0:F][4H] -> g_Wxt[n][k], tf32-rounded ----------------
__global__ void prep_wxt_kernel(const float* __restrict__ W) {
    __shared__ float sm[32][33];
    int k0 = blockIdx.x * 32;
    int n0 = blockIdx.y * 32;
    int tx = threadIdx.x & 31;
    int ty = threadIdx.x >> 5;
#pragma unroll
    for (int r = 0; r < 4; r++) {
        int row = ty + r * 8;
        sm[row][tx] = W[(size_t)(k0 + row) * N4H + n0 + tx];
    }
    __syncthreads();
#pragma unroll
    for (int r = 0; r < 4; r++) {
        int row = ty + r * 8;
        g_Wxt[(size_t)(n0 + row) * FSZ + k0 + tx] = __uint_as_float(tf32r(sm[tx][row]));
    }
}

// ---------------- precompute Z = X @ Wx + b (tf32 mma.sync, 128x64 tile) ----------------
// grid = (64 n-tiles, 64 m-tiles), block=256 (8 warps, 4(M)x2(N), warp tile 32x32)
__global__ __launch_bounds__(256, 2)
void precompute_mma_kernel(const float* __restrict__ X, const float* __restrict__ bias,
                           float* __restrict__ Z) {
    extern __shared__ char dsm_raw[];
    const uint32_t raw_base = smem_u32(dsm_raw);
    const uint32_t base     = (raw_base + 1023) & ~1023u;

    const int tid  = threadIdx.x;
    const int wid  = tid >> 5;
    const int lane = tid & 31;
    const int wm   = wid >> 1;          // 0..3
    const int wn   = wid & 1;           // 0..1
    const int n0   = blockIdx.x * 64;
    const int m0   = blockIdx.y * 128;

    const int grp = lane >> 3;
    const int r_l = lane & 7;
    const int a_row0 = wm * 32 + ((grp & 1) << 3) + r_l;   // mf=0
    const int a_row1 = a_row0 + 16;                         // mf=1
    const int a_cko  = grp >> 1;
    const int b_row0 = wn * 32 + ((grp >> 1) << 3) + r_l;
    const int b_row1 = b_row0 + 16;
    const int b_cko  = grp & 1;

    float c[2][4][4];
#pragma unroll
    for (int mf = 0; mf < 2; mf++)
#pragma unroll
        for (int j = 0; j < 4; j++)
#pragma unroll
            for (int q = 0; q < 4; q++) c[mf][j][q] = 0.0f;

    auto load_tile = [&](int kt, int s) {
        const uint32_t aB = base + s * PC_STAGE_BYTES;
        const uint32_t bB = aB + 32768;
        const int k0 = kt * 64;
#pragma unroll
        for (int i = 0; i < 8; i++) {
            int id = tid + i * 256;
            int row = id >> 4;
            int ck  = id & 15;
            CP16(aB + row * 256 + (((uint32_t)ck ^ (row & 7)) << 4),
                 X + (size_t)(m0 + row) * FSZ + k0 + ck * 4);
        }
#pragma unroll
        for (int i = 0; i < 4; i++) {
            int id = tid + i * 256;
            int row = id >> 4;
            int ck  = id & 15;
            CP16(bB + row * 256 + (((uint32_t)ck ^ (row & 7)) << 4),
                 g_Wxt + (size_t)(n0 + row) * FSZ + k0 + ck * 4);
        }
    };

    load_tile(0, 0);
    CP_COMMIT();

    for (int kt = 0; kt < FSZ / 64; kt++) {
        if (kt + 1 < FSZ / 64) {
            load_tile(kt + 1, (kt + 1) & 1);
            CP_COMMIT();
            CP_WAIT1();
        } else {
            CP_WAIT0();
        }
        __syncthreads();

        const uint32_t aB = base + (kt & 1) * PC_STAGE_BYTES;
        const uint32_t bB = aB + 32768;
#pragma unroll
        for (int ks = 0; ks < 8; ks++) {
            uint32_t u = (uint32_t)(ks * 2);
            uint32_t a00, a01, a02, a03, a10, a11, a12, a13;
            LDSM_X4(a00, a01, a02, a03,
                    aB + a_row0 * 256 + (((u + a_cko) ^ (a_row0 & 7)) << 4));
            LDSM_X4(a10, a11, a12, a13,
                    aB + a_row1 * 256 + (((u + a_cko) ^ (a_row1 & 7)) << 4));

            uint32_t b00, b01, b10, b11, b20, b21, b30, b31;
            LDSM_X4(b00, b01, b10, b11,
                    bB + b_row0 * 256 + (((u + b_cko) ^ (b_row0 & 7)) << 4));
            LDSM_X4(b20, b21, b30, b31,
                    bB + b_row1 * 256 + (((u + b_cko) ^ (b_row1 & 7)) << 4));

            MMA_TF32(c[0][0], a00, a01, a02, a03, b00, b01);
            MMA_TF32(c[0][1], a00, a01, a02, a03, b10, b11);
            MMA_TF32(c[0][2], a00, a01, a02, a03, b20, b21);
            MMA_TF32(c[0][3], a00, a01, a02, a03, b30, b31);
            MMA_TF32(c[1][0], a10, a11, a12, a13, b00, b01);
            MMA_TF32(c[1][1], a10, a11, a12, a13, b10, b11);
            MMA_TF32(c[1][2], a10, a11, a12, a13, b20, b21);
            MMA_TF32(c[1][3], a10, a11, a12, a13, b30, b31);
        }
        __syncthreads();
    }

    // epilogue: add bias, write to Z[t][b][n]; m -> (b = m>>7, t = m&127)
    const int gr = lane >> 2;
    const int qc = lane & 3;
#pragma unroll
    for (int mf = 0; mf < 2; mf++) {
#pragma unroll
        for (int j = 0; j < 4; j++) {
            int n = n0 + wn * 32 + j * 8 + 2 * qc;
            float2 bia = *(const float2*)(bias + n);
            int m1 = m0 + wm * 32 + mf * 16 + gr;
            int m2 = m1 + 8;
            float2 v1 = { c[mf][j][0] + bia.x, c[mf][j][1] + bia.y };
            float2 v2 = { c[mf][j][2] + bia.x, c[mf][j][3] + bia.y };
            *(float2*)(Z + ((size_t)(m1 & 127) * BSZ + (m1 >> 7)) * N4H + n) = v1;
            *(float2*)(Z + ((size_t)(m2 & 127) * BSZ + (m2 >> 7)) * N4H + n) = v2;
        }
    }
}

// ---------------- persistent LSTM kernel ----------------
// grid=128, block=512. 4 k-groups (g = wid>>2) x 4 warps (2(M)x2(N), warp tile 16x32).
// Group g covers k in [g*256, (g+1)*256), KT=32, 8 k-tiles, group-local named barriers.
__global__ __launch_bounds__(512, 1)
void lstm_persist_kernel(float* __restrict__ d_out) {
    extern __shared__ char dsm_raw[];
    __shared__ float c_sm[512];           // cell state [b*8 + j]
    __shared__ float Zs[4 * 512];         // Z staging [gate][b*8+j]

    const uint32_t raw_base = smem_u32(dsm_raw);
    const uint32_t base     = (raw_base + 1023) & ~1023u;
    const uint32_t aS       = base;
    const uint32_t zsB      = smem_u32(Zs);
    float* SfAll = (float*)(dsm_raw + (base - raw_base) + A_SMEM_BYTES); // partials overlay B

    const int tid  = threadIdx.x;
    const int wid  = tid >> 5;
    const int lane = tid & 31;
    const int blk  = blockIdx.x;
    const int g    = wid >> 2;            // k-group 0..3
    const int wg   = wid & 3;
    const int wm   = wg >> 1;             // 0..1
    const int wn   = wg & 1;              // 0..1
    const int tig  = tid & 127;           // thread in group
    const uint32_t bGroup = base + A_SMEM_BYTES + g * BG_BYTES;

    c_sm[tid] = 0.0f;

    // ---- load resident A panel (32 x 1024 f32, swizzled) ----
    {
        const float* wsrc = g_Wr + (size_t)blk * MT * HSZ;
#pragma unroll
        for (int i = 0; i < 16; i++) {
            int u = tid + i * 512;
            int m  = u >> 8;
            int ck = u & 255;
            CP16(aS + m * 4096 + (((uint32_t)ck ^ (m & 7)) << 4), wsrc + (size_t)u * 4);
        }
        CP_COMMIT();
        CP_WAIT0();
    }
    __syncthreads();

    // lane-dependent ldmatrix address components
    const int grp = lane >> 3;
    const int r_l = lane & 7;
    const int a_row  = wm * 16 + ((grp & 1) << 3) + r_l;
    const int a_cko  = grp >> 1;
    const int b_row0 = wn * 32 + ((grp >> 1) << 3) + r_l;
    const int b_row1 = b_row0 + 16;
    const int b_cko  = grp & 1;
    const uint32_t aRowBase = aS + a_row * 4096;

    // epilogue indices
    const int e_j = tid & 7;
    const int e_b = tid >> 3;
    const int e_hcol = blk * 8 + e_j;

    for (int t = 0; t < TSTEPS; t++) {
        const float* __restrict__ hi = g_h[t & 1];
        float* __restrict__ ho = g_h[(t + 1) & 1];

        float c[4][4];
#pragma unroll
        for (int j = 0; j < 4; j++)
#pragma unroll
            for (int q = 0; q < 4; q++) c[j][q] = 0.0f;

        // prefetch Z(t) (all threads) + B tile 0 (per group)
        {
            const float* zt = g_Z + (size_t)t * BSZ * N4H;
            int chunk = tid >> 1, half = tid & 1;
            int zg = chunk & 3, zb = chunk >> 2;
            CP16(zsB + ((uint32_t)(zg * 512 + zb * 8 + half * 4) << 2),
                 zt + (size_t)zb * N4H + zg * HSZ + blk * 8 + half * 4);

            const uint32_t bB = bGroup;
            const int k0 = g * 256;
#pragma unroll
            for (int i = 0; i < 4; i++) {
                int id = tig + i * 128;
                int row = id >> 3;
                int ck  = id & 7;
                CP16(bB + row * 128 + (((uint32_t)ck ^ (row & 7)) << 4),
                     hi + (size_t)row * HSZ + k0 + ck * 4);
            }
            CP_COMMIT();
        }

        for (int kt = 0; kt < 8; kt++) {
            if (kt + 1 < 8) {
                const uint32_t bB = bGroup + ((kt + 1) & 1) * 8192;
                const int k0 = g * 256 + (kt + 1) * 32;
#pragma unroll
                for (int i = 0; i < 4; i++) {
                    int id = tig + i * 128;
                    int row = id >> 3;
                    int ck  = id & 7;
                    CP16(bB + row * 128 + (((uint32_t)ck ^ (row & 7)) << 4),
                         hi + (size_t)row * HSZ + k0 + ck * 4);
                }
                CP_COMMIT();
                CP_WAIT1();
            } else {
                CP_WAIT0();
            }
            BARG(g + 1);

            const uint32_t bB = bGroup + (kt & 1) * 8192;
#pragma unroll
            for (int ks = 0; ks < 4; ks++) {
                uint32_t a0, a1, a2, a3;
                uint32_t aAddr = aRowBase +
                    (((uint32_t)(g * 64 + kt * 8 + ks * 2 + a_cko) ^ (a_row & 7)) << 4);
                LDSM_X4(a0, a1, a2, a3, aAddr);

                uint32_t b00, b01, b10, b11, b20, b21, b30, b31;
                LDSM_X4(b00, b01, b10, b11,
                        bB + b_row0 * 128 + (((uint32_t)(ks * 2 + b_cko) ^ (b_row0 & 7)) << 4));
                LDSM_X4(b20, b21, b30, b31,
                        bB + b_row1 * 128 + (((uint32_t)(ks * 2 + b_cko) ^ (b_row1 & 7)) << 4));

                MMA_TF32(c[0], a0, a1, a2, a3, b00, b01);
                MMA_TF32(c[1], a0, a1, a2, a3, b10, b11);
                MMA_TF32(c[2], a0, a1, a2, a3, b20, b21);
                MMA_TF32(c[3], a0, a1, a2, a3, b30, b31);
            }
            BARG(g + 1);
        }

        // ---- stash partials into own group region: S[m][n] stride 65 ----
        {
            float* S = SfAll + g * 4096;
            const int gr = lane >> 2;
            const int qc = lane & 3;
#pragma unroll
            for (int j = 0; j < 4; j++) {
                int n = wn * 32 + j * 8 + 2 * qc;
                int m = wm * 16 + gr;
                S[m * 65 + n]           = c[j][0];
                S[m * 65 + n + 1]       = c[j][1];
                S[(m + 8) * 65 + n]     = c[j][2];
                S[(m + 8) * 65 + n + 1] = c[j][3];
            }
        }
        __syncthreads();

        // ---- gate epilogue: 512 cells, 1 per thread ----
        float h_new;
        {
            float z[4];
#pragma unroll
            for (int gate = 0; gate < 4; gate++) {
                float s = Zs[gate * 512 + tid];
#pragma unroll
                for (int g2 = 0; g2 < 4; g2++)
                    s += SfAll[g2 * 4096 + (gate * 8 + e_j) * 65 + e_b];
                z[gate] = s;
            }
            float c_old = c_sm[tid];
            float si = 1.0f / (1.0f + __expf(-z[0]));
            float sf = 1.0f / (1.0f + __expf(-(z[2] + 1.0f)));   // forget bias = 1.0
            float so = 1.0f / (1.0f + __expf(-z[3]));
            float tj = tanhf(z[1]);

            float c_new = c_old * sf + si * tj;
            h_new = tanhf(c_new) * so;

            c_sm[tid] = c_new;
            ho[(size_t)e_b * HSZ + e_hcol] = h_new;
        }

        if (t == TSTEPS - 1) {
            d_out[((size_t)e_b * TSTEPS + t) * HSZ + e_hcol] = h_new;
            break;
        }

        // ---- grid barrier, with d_out store overlapped ----
        __threadfence();
        __syncthreads();
        unsigned gen = 0;
        if (tid == 0) {
            gen = g_bar_gen;
            if (atomicAdd(&g_bar_count, 1u) == NCTA - 1) {
                g_bar_count = 0;
                __threadfence();
                g_bar_gen = gen + 1;
            }
        }
        d_out[((size_t)e_b * TSTEPS + t) * HSZ + e_hcol] = h_new;
        if (tid == 0) {
            while (g_bar_gen == gen) { }
        }
        __syncthreads();
    }
}

// ---------------- launcher ----------------
extern "C" void kernel_launch(void* const* d_in, const int* in_sizes, int n_in,
                              void* d_out, int out_size) {
    const float* x = (const float*)d_in[0];   // [B, T, F]
    const float* W = (const float*)d_in[1];   // [F+H, 4H]
    const float* b = (const float*)d_in[2];   // [4H]
    float* out = (float*)d_out;               // [B, T, H]

    static bool attr_done = false;
    if (!attr_done) {
        cudaFuncSetAttribute(lstm_persist_kernel, cudaFuncAttributeMaxDynamicSharedMemorySize,
                             DSMEM_BYTES);
        cudaFuncSetAttribute(precompute_mma_kernel, cudaFuncAttributeMaxDynamicSharedMemorySize,
                             PC_DSMEM);
        attr_done = true;
    }

    float* zbuf;
    cudaGetSymbolAddress((void**)&zbuf, g_Z);

    init_state_kernel<<<(BSZ * HSZ + 255) / 256, 256>>>();
    prep_w_kernel<<<NCTA * 4 * 32, 256>>>(W);
    {
        dim3 g(FSZ / 32, N4H / 32);
        prep_wxt_kernel<<<g, 256>>>(W);
    }
    {
        dim3 g(N4H / 64, (BSZ * TSTEPS) / 128);   // (64, 64)
        precompute_mma_kernel<<<g, 256, PC_DSMEM>>>(x, b, zbuf);
    }
    lstm_persist_kernel<<<NCTA, 512, DSMEM_BYTES>>>(out);
}